// round 5
// baseline (speedup 1.0000x reference)
#include <cuda_runtime.h>

// ----------------------------------------------------------------------------
// SplineCoupling fused kernel (fp32, FFMA path).
// Per CTA: 128 rows, 512 threads.
//   Phase 1: H1 = relu(LN(Xm @ W0 + b0) * g0 + be0)            (K=32)
//   Phase 2: H2 = relu(LN(H1 @ W1 + b1) * g1 + be1) + H1       (K=128)
//   Phase 3: for 8 chunks of 4 dims: raw = H2 @ Wp[:,chunk]+bp (K=128),
//            softmax widths/heights, softplus derivs, RQS spline, log-det.
// Output layout: y (B*64 floats) then log_det (B floats).
// ----------------------------------------------------------------------------

namespace {
constexpr int kB       = 262144;
constexpr int kRows    = 128;
constexpr int kThreads = 512;

// shared memory layout (bytes). Regions re-used across phases (sync-separated).
constexpr int XM_OFF = 0;                        // 128*33 f  (persistent)
constexpr int XU_OFF = XM_OFF + 128 * 33 * 4;    // 16896: xu, later yu
constexpr int BP_OFF = XU_OFF + 128 * 33 * 4;    // 33792: bp (800 f)
constexpr int BV_OFF = BP_OFF + 800 * 4;         // 36992: b0,g0,be0,b1,g1,be1
constexpr int H_OFF  = BV_OFF + 768 * 4;         // 40064: 128*129 f (H1 then H2)
constexpr int W1_OFF = H_OFF + 128 * 129 * 4;    // 106112: 128*128 f (phase 1-2)
constexpr int WP_OFF = W1_OFF;                   // phase 3: 2 x 128*112 f
constexpr int W0_OFF = W1_OFF + 128 * 128 * 4;   // 171648: 32*128 f (phase 1)
constexpr int SMEM_BYTES = WP_OFF + 2 * 128 * 112 * 4;   // 220800
static_assert(W0_OFF + 32 * 128 * 4 <= SMEM_BYTES, "w0 fits");
}  // namespace

__global__ void __launch_bounds__(512, 1) spline_fused_kernel(
    const float* __restrict__ x,
    const float* __restrict__ W0, const float* __restrict__ b0,
    const float* __restrict__ g0, const float* __restrict__ be0,
    const float* __restrict__ W1, const float* __restrict__ b1,
    const float* __restrict__ g1, const float* __restrict__ be1,
    const float* __restrict__ Wp, const float* __restrict__ bp,
    float* __restrict__ out)
{
    extern __shared__ char smem[];
    float* sXM = reinterpret_cast<float*>(smem + XM_OFF);
    float* sXU = reinterpret_cast<float*>(smem + XU_OFF);
    float* sBP = reinterpret_cast<float*>(smem + BP_OFF);
    float* sBV = reinterpret_cast<float*>(smem + BV_OFF);
    float* sH  = reinterpret_cast<float*>(smem + H_OFF);    // H1, then H2
    float* sW1 = reinterpret_cast<float*>(smem + W1_OFF);
    float* sWP = reinterpret_cast<float*>(smem + WP_OFF);   // 2 buffers
    float* sW0 = reinterpret_cast<float*>(smem + W0_OFF);

    const int tid = threadIdx.x;
    const int r0  = blockIdx.x * kRows;

    // ---------------- cooperative loads ----------------
    {
        const float4* xg = reinterpret_cast<const float4*>(x + (size_t)r0 * 64);
        #pragma unroll
        for (int i = tid; i < kRows * 16; i += kThreads) {
            int r = i >> 4, v = i & 15;
            float4 f = xg[i];
            sXM[r * 33 + 2 * v]     = f.x;
            sXU[r * 33 + 2 * v]     = f.y;
            sXM[r * 33 + 2 * v + 1] = f.z;
            sXU[r * 33 + 2 * v + 1] = f.w;
        }
        const float4* w0g = reinterpret_cast<const float4*>(W0);
        #pragma unroll
        for (int i = tid; i < (32 * 128) / 4; i += kThreads)
            reinterpret_cast<float4*>(sW0)[i] = w0g[i];
        const float4* w1g = reinterpret_cast<const float4*>(W1);
        #pragma unroll
        for (int i = tid; i < (128 * 128) / 4; i += kThreads)
            reinterpret_cast<float4*>(sW1)[i] = w1g[i];
        const float4* bpg = reinterpret_cast<const float4*>(bp);
        #pragma unroll
        for (int i = tid; i < 800 / 4; i += kThreads)
            reinterpret_cast<float4*>(sBP)[i] = bpg[i];
        if (tid < 128) {
            sBV[tid]       = b0[tid];
            sBV[128 + tid] = g0[tid];
            sBV[256 + tid] = be0[tid];
            sBV[384 + tid] = b1[tid];
            sBV[512 + tid] = g1[tid];
            sBV[640 + tid] = be1[tid];
        }
    }
    __syncthreads();

    // ---------------- Phase 1: GEMM1 + LN + relu -> sH (H1) ----------------
    {
        const int row = tid >> 2, q = tid & 3;          // 4 threads per row
        float accf[32];
        #pragma unroll
        for (int i = 0; i < 32; i++) accf[i] = 0.f;
        const float* a = sXM + row * 33;
        const float* wbase = sW0 + q * 32;
        #pragma unroll 4
        for (int k = 0; k < 32; k++) {
            float av = a[k];
            const float4* w4 = reinterpret_cast<const float4*>(wbase + k * 128);
            #pragma unroll
            for (int i = 0; i < 8; i++) {
                float4 w = w4[i];
                accf[4 * i + 0] += av * w.x;
                accf[4 * i + 1] += av * w.y;
                accf[4 * i + 2] += av * w.z;
                accf[4 * i + 3] += av * w.w;
            }
        }
        float s1 = 0.f, s2 = 0.f;
        #pragma unroll
        for (int i = 0; i < 32; i++) {
            float v = accf[i] + sBV[q * 32 + i];        // + b0
            accf[i] = v;
            s1 += v;
            s2 += v * v;
        }
        s1 += __shfl_xor_sync(0xffffffffu, s1, 1);
        s1 += __shfl_xor_sync(0xffffffffu, s1, 2);
        s2 += __shfl_xor_sync(0xffffffffu, s2, 1);
        s2 += __shfl_xor_sync(0xffffffffu, s2, 2);
        float mu   = s1 * (1.f / 128.f);
        float var  = s2 * (1.f / 128.f) - mu * mu;
        float rstd = rsqrtf(var + 1e-6f);
        float* hrow = sH + row * 129 + q * 32;
        #pragma unroll
        for (int i = 0; i < 32; i++) {
            int c = q * 32 + i;
            float hv = (accf[i] - mu) * rstd * sBV[128 + c] + sBV[256 + c];
            hrow[i] = fmaxf(hv, 0.f);
        }
    }
    __syncthreads();

    // ---------------- Phase 2: GEMM2 + LN + relu + residual -> sH (H2) -----
    float H2a[16], H2b[16];
    {
        const int rp = tid >> 3, cg = tid & 7;          // 2 rows x 16 cols
        const float* a0 = sH + (2 * rp) * 129;
        const float* a1 = a0 + 129;
        float A0[16], A1[16];
        #pragma unroll
        for (int i = 0; i < 16; i++) { A0[i] = 0.f; A1[i] = 0.f; }
        const float* wbase = sW1 + cg * 16;
        #pragma unroll 4
        for (int k = 0; k < 128; k++) {
            float av0 = a0[k], av1 = a1[k];
            const float4* w4 = reinterpret_cast<const float4*>(wbase + k * 128);
            #pragma unroll
            for (int i = 0; i < 4; i++) {
                float4 w = w4[i];
                A0[4 * i + 0] += av0 * w.x;  A1[4 * i + 0] += av1 * w.x;
                A0[4 * i + 1] += av0 * w.y;  A1[4 * i + 1] += av1 * w.y;
                A0[4 * i + 2] += av0 * w.z;  A1[4 * i + 2] += av1 * w.z;
                A0[4 * i + 3] += av0 * w.w;  A1[4 * i + 3] += av1 * w.w;
            }
        }
        float s1a = 0.f, s2a = 0.f, s1b = 0.f, s2b = 0.f;
        #pragma unroll
        for (int i = 0; i < 16; i++) {
            int c = cg * 16 + i;
            float v0 = A0[i] + sBV[384 + c];            // + b1
            float v1 = A1[i] + sBV[384 + c];
            A0[i] = v0; A1[i] = v1;
            s1a += v0; s2a += v0 * v0;
            s1b += v1; s2b += v1 * v1;
        }
        #pragma unroll
        for (int d = 1; d < 8; d <<= 1) {
            s1a += __shfl_xor_sync(0xffffffffu, s1a, d);
            s2a += __shfl_xor_sync(0xffffffffu, s2a, d);
            s1b += __shfl_xor_sync(0xffffffffu, s1b, d);
            s2b += __shfl_xor_sync(0xffffffffu, s2b, d);
        }
        float mua = s1a * (1.f / 128.f);
        float rsa = rsqrtf(s2a * (1.f / 128.f) - mua * mua + 1e-6f);
        float mub = s1b * (1.f / 128.f);
        float rsb = rsqrtf(s2b * (1.f / 128.f) - mub * mub + 1e-6f);
        #pragma unroll
        for (int i = 0; i < 16; i++) {
            int c = cg * 16 + i;
            float gg = sBV[512 + c], bb = sBV[640 + c];
            float h0 = fmaxf((A0[i] - mua) * rsa * gg + bb, 0.f) + a0[c];  // residual
            float h1v = fmaxf((A1[i] - mub) * rsb * gg + bb, 0.f) + a1[c];
            H2a[i] = h0;
            H2b[i] = h1v;
        }
    }
    __syncthreads();   // all H1 reads done; sH can be overwritten with H2
    {
        const int rp = tid >> 3, cg = tid & 7;
        float* d0 = sH + (2 * rp) * 129 + cg * 16;
        float* d1 = d0 + 129;
        #pragma unroll
        for (int i = 0; i < 16; i++) { d0[i] = H2a[i]; d1[i] = H2b[i]; }
    }
    __syncthreads();

    // ---------------- Phase 3: GEMM3 chunks + spline epilogue --------------
    const int row  = tid >> 2;
    const int dimq = tid & 3;
    const float* h2row = sH + row * 129;
    float* bufs0 = sWP;
    float* bufs1 = sWP + 128 * 112;
    float ld_acc = 0.f;

    // load chunk 0 (dims 0..3 -> cols 0..99 of Wp)
    #pragma unroll
    for (int t = 0; t < 25; t++) {
        int i = tid + t * 512;
        int k = i / 100, m = i - k * 100;
        int ld = m / 25, j = m - ld * 25;
        bufs0[k * 112 + ld * 28 + j] = Wp[k * 800 + m];
    }
    __syncthreads();

    for (int c = 0; c < 8; c++) {
        const float* wp  = (c & 1) ? bufs1 : bufs0;
        float*       wpn = (c & 1) ? bufs0 : bufs1;

        // prefetch next chunk into registers (latency hidden behind k-loop)
        float pf[25];
        if (c < 7) {
            #pragma unroll
            for (int t = 0; t < 25; t++) {
                int i = tid + t * 512;
                int k = i / 100, m = i - k * 100;
                pf[t] = Wp[k * 800 + (c + 1) * 100 + m];
            }
        }

        // K=128 dot products: 25 outputs for this (row, dim)
        float accf[25];
        #pragma unroll
        for (int j = 0; j < 25; j++) accf[j] = 0.f;
        const float* wsec = wp + dimq * 28;
        #pragma unroll 2
        for (int k = 0; k < 128; k++) {
            float av = h2row[k];
            const float4* w4 = reinterpret_cast<const float4*>(wsec + k * 112);
            #pragma unroll
            for (int i = 0; i < 6; i++) {
                float4 w = w4[i];
                accf[4 * i + 0] += av * w.x;
                accf[4 * i + 1] += av * w.y;
                accf[4 * i + 2] += av * w.z;
                accf[4 * i + 3] += av * w.w;
            }
            accf[24] += av * wsec[k * 112 + 24];
        }

        // stage the prefetched chunk (target buffer was last read 2 iters ago)
        if (c < 7) {
            #pragma unroll
            for (int t = 0; t < 25; t++) {
                int i = tid + t * 512;
                int k = i / 100, m = i - k * 100;
                int ld = m / 25, j = m - ld * 25;
                wpn[k * 112 + ld * 28 + j] = pf[t];
            }
        }

        // ---------------- spline epilogue (all register-local) ----------------
        const int dimg = c * 4 + dimq;
        const float* bpd = sBP + dimg * 25;
        float wr[8], hr[8], dr9[9];
        #pragma unroll
        for (int j = 0; j < 8; j++) wr[j] = accf[j] + bpd[j];
        #pragma unroll
        for (int j = 0; j < 8; j++) hr[j] = accf[8 + j] + bpd[8 + j];
        #pragma unroll
        for (int j = 0; j < 9; j++) dr9[j] = accf[16 + j] + bpd[16 + j];

        // softmax widths
        float mw = wr[0];
        #pragma unroll
        for (int j = 1; j < 8; j++) mw = fmaxf(mw, wr[j]);
        float ew[8], sw = 0.f;
        #pragma unroll
        for (int j = 0; j < 8; j++) { ew[j] = __expf(wr[j] - mw); sw += ew[j]; }
        float scw = 5.952f / sw;                         // (1 - 8*0.001) * 6
        float w[8];
        #pragma unroll
        for (int j = 0; j < 8; j++) w[j] = 0.006f + ew[j] * scw;

        // softmax heights
        float mh = hr[0];
        #pragma unroll
        for (int j = 1; j < 8; j++) mh = fmaxf(mh, hr[j]);
        float eh[8], sh = 0.f;
        #pragma unroll
        for (int j = 0; j < 8; j++) { eh[j] = __expf(hr[j] - mh); sh += eh[j]; }
        float sch = 5.952f / sh;
        float h[8];
        #pragma unroll
        for (int j = 0; j < 8; j++) h[j] = 0.006f + eh[j] * sch;

        // softplus derivatives
        float dv[9];
        #pragma unroll
        for (int j = 0; j < 9; j++) {
            float xx = dr9[j];
            dv[j] = fmaxf(xx, 0.f) + log1pf(__expf(-fabsf(xx))) + 0.001f;
        }

        float xu = sXU[row * 33 + dimg];
        bool inside = (xu > -3.f) && (xu < 3.f);
        float xc = fminf(fmaxf(xu, -3.f), 3.f);

        float cwv[9], chv[9];
        cwv[0] = -3.f; chv[0] = -3.f;
        #pragma unroll
        for (int j = 0; j < 8; j++) {
            cwv[j + 1] = cwv[j] + w[j];
            chv[j + 1] = chv[j] + h[j];
        }
        int idx = 0;
        #pragma unroll
        for (int j = 1; j <= 8; j++) idx += (xc >= cwv[j]) ? 1 : 0;
        idx = min(idx, 7);

        float w_k = w[0], x_k = cwv[0], h_k = h[0], y_k = chv[0];
        float d_k = dv[0], d_k1 = dv[1];
        #pragma unroll
        for (int j = 1; j < 8; j++) {
            if (idx == j) {
                w_k = w[j]; x_k = cwv[j]; h_k = h[j]; y_k = chv[j];
                d_k = dv[j]; d_k1 = dv[j + 1];
            }
        }
        float s   = h_k / w_k;
        float th  = (xc - x_k) / w_k;
        float om  = 1.f - th;
        float t1m = th * om;
        float den = s + (d_k1 + d_k - 2.f * s) * t1m;
        float yin = y_k + h_k * (s * th * th + d_k * t1m) / den;
        float num = d_k1 * th * th + 2.f * s * t1m + d_k * om * om;
        float ldin = 2.f * __logf(s) + __logf(num) - 2.f * __logf(den);

        sXU[row * 33 + dimg] = inside ? yin : xu;       // slot reused as yu
        ld_acc += inside ? ldin : 0.f;

        __syncthreads();
    }

    // log_det: reduce over the 4 dimq threads of this row
    ld_acc += __shfl_xor_sync(0xffffffffu, ld_acc, 1);
    ld_acc += __shfl_xor_sync(0xffffffffu, ld_acc, 2);
    if (dimq == 0) out[(size_t)kB * 64 + r0 + row] = ld_acc;

    // final y write: interleave xm (even) / yu (odd), fully coalesced float2
    float2* outg = reinterpret_cast<float2*>(out + (size_t)r0 * 64);
    #pragma unroll
    for (int i = tid; i < kRows * 32; i += kThreads) {
        int r = i >> 5, j = i & 31;
        outg[i] = make_float2(sXM[r * 33 + j], sXU[r * 33 + j]);
    }
}

extern "C" void kernel_launch(void* const* d_in, const int* in_sizes, int n_in,
                              void* d_out, int out_size)
{
    (void)in_sizes; (void)n_in; (void)out_size;
    const float* x   = (const float*)d_in[0];
    const float* W0  = (const float*)d_in[1];
    const float* b0  = (const float*)d_in[2];
    const float* g0  = (const float*)d_in[3];
    const float* be0 = (const float*)d_in[4];
    const float* W1  = (const float*)d_in[5];
    const float* b1  = (const float*)d_in[6];
    const float* g1  = (const float*)d_in[7];
    const float* be1 = (const float*)d_in[8];
    const float* Wp  = (const float*)d_in[9];
    const float* bp  = (const float*)d_in[10];
    float* out = (float*)d_out;

    cudaFuncSetAttribute(spline_fused_kernel,
                         cudaFuncAttributeMaxDynamicSharedMemorySize, SMEM_BYTES);
    spline_fused_kernel<<<kB / kRows, kThreads, SMEM_BYTES>>>(
        x, W0, b0, g0, be0, W1, b1, g1, be1, Wp, bp, out);
}

// round 6
// speedup vs baseline: 2.2195x; 2.2195x over previous
#include <cuda_runtime.h>

// ----------------------------------------------------------------------------
// SplineCoupling fused kernel, round 6: register-tiled FFMA GEMMs.
// Per CTA: 128 rows, 512 threads, 1 CTA/SM (222KB smem).
//  Phase 1: H1 = relu(LN(Xm @ W0 + b0)*g0+be0)     tile 4r x 8c (strided cols)
//  Phase 2: H2 = relu(LN(H1 @ W1 + b1)*g1+be1)+H1  tile 4r x 8c; H2 stored
//           transposed (H2T[k][row]) for vectorized phase-3 A loads.
//  Phase 3: 8 chunks x (GEMM 128x100x128, tile 8r x 4c, 400 threads) ->
//           raw to smem -> spline epilogue thread-per-(row,dim).
// ----------------------------------------------------------------------------

namespace {
constexpr int kB       = 262144;
constexpr int kRows    = 128;
constexpr int kThreads = 512;

// float offsets in dynamic smem
constexpr int XU_OFF = 0;                    // 128*33   : xu, later yu
constexpr int BP_OFF = XU_OFF + 128 * 33;    // 800      : bp
constexpr int BV_OFF = BP_OFF + 800;         // 768      : b0,g0,be0,b1,g1,be1
constexpr int H_OFF  = BV_OFF + 768;         // 128*129  : xm -> H1 -> raw
constexpr int HT_OFF = H_OFF + 128 * 129;    // 128*132  : H2 transposed
constexpr int R_OFF  = HT_OFF + 128 * 132;   // 16384    : W0 -> W1 -> Wp chunk
constexpr int SMEM_FLOATS = R_OFF + 16384;   // 55584
constexpr int SMEM_BYTES  = SMEM_FLOATS * 4; // 222336
}  // namespace

__global__ void __launch_bounds__(512, 1) spline_fused_kernel(
    const float* __restrict__ x,
    const float* __restrict__ W0, const float* __restrict__ b0,
    const float* __restrict__ g0, const float* __restrict__ be0,
    const float* __restrict__ W1, const float* __restrict__ b1,
    const float* __restrict__ g1, const float* __restrict__ be1,
    const float* __restrict__ Wp, const float* __restrict__ bp,
    float* __restrict__ out)
{
    extern __shared__ float sm[];
    float* sXU = sm + XU_OFF;
    float* sBP = sm + BP_OFF;
    float* sBV = sm + BV_OFF;
    float* sH  = sm + H_OFF;    // xm (row*33+k) -> H1 (row*129+c) -> raw (row*105+c)
    float* sHT = sm + HT_OFF;   // H2T (k*132 + row)
    float* sR  = sm + R_OFF;    // W0 -> W1 -> Wp chunk (k*104 + c)

    const int tid = threadIdx.x;
    const int r0  = blockIdx.x * kRows;

    // ---------------- cooperative loads ----------------
    {
        const float4* xg = reinterpret_cast<const float4*>(x + (size_t)r0 * 64);
        #pragma unroll
        for (int i = tid; i < kRows * 16; i += kThreads) {
            int r = i >> 4, v = i & 15;
            float4 f = xg[i];
            sH [r * 33 + 2 * v]     = f.x;   // xm
            sXU[r * 33 + 2 * v]     = f.y;
            sH [r * 33 + 2 * v + 1] = f.z;
            sXU[r * 33 + 2 * v + 1] = f.w;
        }
        const float4* w0g = reinterpret_cast<const float4*>(W0);
        #pragma unroll
        for (int i = tid; i < (32 * 128) / 4; i += kThreads)
            reinterpret_cast<float4*>(sR)[i] = w0g[i];
        const float4* bpg = reinterpret_cast<const float4*>(bp);
        #pragma unroll
        for (int i = tid; i < 200; i += kThreads)
            reinterpret_cast<float4*>(sBP)[i] = bpg[i];
        if (tid < 128) {
            sBV[tid]       = b0[tid];
            sBV[128 + tid] = g0[tid];
            sBV[256 + tid] = be0[tid];
            sBV[384 + tid] = b1[tid];
            sBV[512 + tid] = g1[tid];
            sBV[640 + tid] = be1[tid];
        }
    }
    __syncthreads();

    const int rg = tid >> 4;     // 0..31 : 4-row group
    const int cg = tid & 15;     // 0..15 : col lane (cols cg + 16*i)

    // ---------------- Phase 1: GEMM1 (K=32) tile 4x8 ----------------
    float acc[4][8];
    #pragma unroll
    for (int r = 0; r < 4; r++)
        #pragma unroll
        for (int i = 0; i < 8; i++) acc[r][i] = 0.f;

    #pragma unroll 4
    for (int k = 0; k < 32; k++) {
        float a[4];
        #pragma unroll
        for (int r = 0; r < 4; r++) a[r] = sH[(rg * 4 + r) * 33 + k];
        #pragma unroll
        for (int i = 0; i < 8; i++) {
            float b = sR[k * 128 + cg + 16 * i];
            #pragma unroll
            for (int r = 0; r < 4; r++) acc[r][i] += a[r] * b;
        }
    }
    __syncthreads();   // xm & W0 reads done; sH/sR reusable

    {
        // prefetch W1 into registers (latency hidden behind LN + H1 store)
        float4 w1pf[8];
        const float4* w1g = reinterpret_cast<const float4*>(W1);
        #pragma unroll
        for (int t = 0; t < 8; t++) w1pf[t] = w1g[tid + t * 512];

        // bias + LN + relu
        float mu[4], rs[4];
        #pragma unroll
        for (int r = 0; r < 4; r++) {
            float s1 = 0.f, s2 = 0.f;
            #pragma unroll
            for (int i = 0; i < 8; i++) {
                float v = acc[r][i] + sBV[cg + 16 * i];
                acc[r][i] = v;
                s1 += v; s2 += v * v;
            }
            #pragma unroll
            for (int d = 1; d < 16; d <<= 1) {
                s1 += __shfl_xor_sync(0xffffffffu, s1, d);
                s2 += __shfl_xor_sync(0xffffffffu, s2, d);
            }
            mu[r] = s1 * (1.f / 128.f);
            rs[r] = rsqrtf(s2 * (1.f / 128.f) - mu[r] * mu[r] + 1e-6f);
        }
        #pragma unroll
        for (int i = 0; i < 8; i++) {
            int c = cg + 16 * i;
            float gg = sBV[128 + c], bb = sBV[256 + c];
            #pragma unroll
            for (int r = 0; r < 4; r++) {
                float h = (acc[r][i] - mu[r]) * rs[r] * gg + bb;
                sH[(rg * 4 + r) * 129 + c] = fmaxf(h, 0.f);   // H1
            }
        }
        // stage W1
        #pragma unroll
        for (int t = 0; t < 8; t++)
            reinterpret_cast<float4*>(sR)[tid + t * 512] = w1pf[t];
    }
    __syncthreads();

    // ---------------- Phase 2: GEMM2 (K=128) tile 4x8 ----------------
    float pfw[25];   // Wp chunk-0 prefetch (in flight during GEMM2)
    #pragma unroll
    for (int t = 0; t < 25; t++) {
        int i = tid + t * 512;
        int k = i / 100, m = i - k * 100;
        pfw[t] = Wp[k * 800 + m];
    }

    #pragma unroll
    for (int r = 0; r < 4; r++)
        #pragma unroll
        for (int i = 0; i < 8; i++) acc[r][i] = 0.f;

    #pragma unroll 4
    for (int k = 0; k < 128; k++) {
        float a[4];
        #pragma unroll
        for (int r = 0; r < 4; r++) a[r] = sH[(rg * 4 + r) * 129 + k];
        #pragma unroll
        for (int i = 0; i < 8; i++) {
            float b = sR[k * 128 + cg + 16 * i];
            #pragma unroll
            for (int r = 0; r < 4; r++) acc[r][i] += a[r] * b;
        }
    }
    {
        float mu[4], rs[4];
        #pragma unroll
        for (int r = 0; r < 4; r++) {
            float s1 = 0.f, s2 = 0.f;
            #pragma unroll
            for (int i = 0; i < 8; i++) {
                float v = acc[r][i] + sBV[384 + cg + 16 * i];
                acc[r][i] = v;
                s1 += v; s2 += v * v;
            }
            #pragma unroll
            for (int d = 1; d < 16; d <<= 1) {
                s1 += __shfl_xor_sync(0xffffffffu, s1, d);
                s2 += __shfl_xor_sync(0xffffffffu, s2, d);
            }
            mu[r] = s1 * (1.f / 128.f);
            rs[r] = rsqrtf(s2 * (1.f / 128.f) - mu[r] * mu[r] + 1e-6f);
        }
        #pragma unroll
        for (int i = 0; i < 8; i++) {
            int c = cg + 16 * i;
            float gg = sBV[512 + c], bb = sBV[640 + c];
            #pragma unroll
            for (int r = 0; r < 4; r++) {
                int row = rg * 4 + r;
                float h = fmaxf((acc[r][i] - mu[r]) * rs[r] * gg + bb, 0.f)
                          + sH[row * 129 + c];                 // residual
                sHT[c * 132 + row] = h;                        // H2 transposed
            }
        }
    }
    __syncthreads();   // W1 reads done; H2T complete

    // stage Wp chunk 0
    #pragma unroll
    for (int t = 0; t < 25; t++) {
        int i = tid + t * 512;
        int k = i / 100, m = i - k * 100;
        sR[k * 104 + m] = pfw[t];
    }
    __syncthreads();

    // ---------------- Phase 3: 8 chunks ----------------
    const int g3rg  = tid / 25;           // 0..15 (8-row group), valid tid<400
    const int g3cg  = tid - g3rg * 25;    // 0..24 (4-col group)
    const bool g3a  = tid < 400;
    const int erow  = tid >> 2;           // epilogue: row
    const int eq    = tid & 3;            // epilogue: dim-in-chunk
    float ld_acc = 0.f;

    for (int c = 0; c < 8; c++) {
        // prefetch next chunk to registers
        if (c < 7) {
            #pragma unroll
            for (int t = 0; t < 25; t++) {
                int i = tid + t * 512;
                int k = i / 100, m = i - k * 100;
                pfw[t] = Wp[k * 800 + (c + 1) * 100 + m];
            }
        }

        // GEMM: 8 rows x 4 cols per thread
        float a3[8][4];
        #pragma unroll
        for (int r = 0; r < 8; r++)
            #pragma unroll
            for (int j = 0; j < 4; j++) a3[r][j] = 0.f;

        if (g3a) {
            const float* at = sHT + g3rg * 8;
            const float* bt = sR + g3cg * 4;
            #pragma unroll 4
            for (int k = 0; k < 128; k++) {
                float4 b  = *reinterpret_cast<const float4*>(bt + k * 104);
                float4 a0 = *reinterpret_cast<const float4*>(at + k * 132);
                float4 a1 = *reinterpret_cast<const float4*>(at + k * 132 + 4);
                float av[8] = {a0.x, a0.y, a0.z, a0.w, a1.x, a1.y, a1.z, a1.w};
                #pragma unroll
                for (int r = 0; r < 8; r++) {
                    a3[r][0] += av[r] * b.x;
                    a3[r][1] += av[r] * b.y;
                    a3[r][2] += av[r] * b.z;
                    a3[r][3] += av[r] * b.w;
                }
            }
            // raw -> smem (stride 105 to dodge bank conflicts in epilogue)
            #pragma unroll
            for (int r = 0; r < 8; r++)
                #pragma unroll
                for (int j = 0; j < 4; j++)
                    sH[(g3rg * 8 + r) * 105 + g3cg * 4 + j] = a3[r][j];
        }
        __syncthreads();

        // stage next weights (all chunk-c reads of sR completed above)
        if (c < 7) {
            #pragma unroll
            for (int t = 0; t < 25; t++) {
                int i = tid + t * 512;
                int k = i / 100, m = i - k * 100;
                sR[k * 104 + m] = pfw[t];
            }
        }

        // ---------------- spline epilogue ----------------
        {
            const int dimg = c * 4 + eq;
            const float* rawp = sH + erow * 105 + eq * 25;
            const float* bpd  = sBP + dimg * 25;
            float wr[8], hr[8], dr9[9];
            #pragma unroll
            for (int j = 0; j < 8; j++) wr[j] = rawp[j] + bpd[j];
            #pragma unroll
            for (int j = 0; j < 8; j++) hr[j] = rawp[8 + j] + bpd[8 + j];
            #pragma unroll
            for (int j = 0; j < 9; j++) dr9[j] = rawp[16 + j] + bpd[16 + j];

            float mw = wr[0];
            #pragma unroll
            for (int j = 1; j < 8; j++) mw = fmaxf(mw, wr[j]);
            float ew[8], sw = 0.f;
            #pragma unroll
            for (int j = 0; j < 8; j++) { ew[j] = __expf(wr[j] - mw); sw += ew[j]; }
            float scw = 5.952f / sw;
            float w[8];
            #pragma unroll
            for (int j = 0; j < 8; j++) w[j] = 0.006f + ew[j] * scw;

            float mh = hr[0];
            #pragma unroll
            for (int j = 1; j < 8; j++) mh = fmaxf(mh, hr[j]);
            float eh[8], shs = 0.f;
            #pragma unroll
            for (int j = 0; j < 8; j++) { eh[j] = __expf(hr[j] - mh); shs += eh[j]; }
            float sch = 5.952f / shs;
            float h[8];
            #pragma unroll
            for (int j = 0; j < 8; j++) h[j] = 0.006f + eh[j] * sch;

            float dv[9];
            #pragma unroll
            for (int j = 0; j < 9; j++) {
                float xx = dr9[j];
                dv[j] = fmaxf(xx, 0.f) + log1pf(__expf(-fabsf(xx))) + 0.001f;
            }

            float xu = sXU[erow * 33 + dimg];
            bool inside = (xu > -3.f) && (xu < 3.f);
            float xc = fminf(fmaxf(xu, -3.f), 3.f);

            float cwv[9], chv[9];
            cwv[0] = -3.f; chv[0] = -3.f;
            #pragma unroll
            for (int j = 0; j < 8; j++) {
                cwv[j + 1] = cwv[j] + w[j];
                chv[j + 1] = chv[j] + h[j];
            }
            int idx = 0;
            #pragma unroll
            for (int j = 1; j <= 8; j++) idx += (xc >= cwv[j]) ? 1 : 0;
            idx = min(idx, 7);

            float w_k = w[0], x_k = cwv[0], h_k = h[0], y_k = chv[0];
            float d_k = dv[0], d_k1 = dv[1];
            #pragma unroll
            for (int j = 1; j < 8; j++) {
                if (idx == j) {
                    w_k = w[j]; x_k = cwv[j]; h_k = h[j]; y_k = chv[j];
                    d_k = dv[j]; d_k1 = dv[j + 1];
                }
            }
            float s   = h_k / w_k;
            float th  = (xc - x_k) / w_k;
            float om  = 1.f - th;
            float t1m = th * om;
            float den = s + (d_k1 + d_k - 2.f * s) * t1m;
            float yin = y_k + h_k * (s * th * th + d_k * t1m) / den;
            float num = d_k1 * th * th + 2.f * s * t1m + d_k * om * om;
            float ldin = 2.f * __logf(s) + __logf(num) - 2.f * __logf(den);

            sXU[erow * 33 + dimg] = inside ? yin : xu;
            ld_acc += inside ? ldin : 0.f;
        }
        __syncthreads();
    }

    // log_det: reduce the 4 dim-threads of each row
    ld_acc += __shfl_xor_sync(0xffffffffu, ld_acc, 1);
    ld_acc += __shfl_xor_sync(0xffffffffu, ld_acc, 2);
    if (eq == 0) out[(size_t)kB * 64 + r0 + erow] = ld_acc;

    // final y: re-read x for xm, interleave with yu; float4 coalesced
    {
        const float4* xg = reinterpret_cast<const float4*>(x + (size_t)r0 * 64);
        float4* og = reinterpret_cast<float4*>(out + (size_t)r0 * 64);
        #pragma unroll
        for (int i = tid; i < kRows * 16; i += kThreads) {
            int r = i >> 4, v = i & 15;
            float4 f = xg[i];
            og[i] = make_float4(f.x, sXU[r * 33 + 2 * v],
                                f.z, sXU[r * 33 + 2 * v + 1]);
        }
    }
}

extern "C" void kernel_launch(void* const* d_in, const int* in_sizes, int n_in,
                              void* d_out, int out_size)
{
    (void)in_sizes; (void)n_in; (void)out_size;
    const float* x   = (const float*)d_in[0];
    const float* W0  = (const float*)d_in[1];
    const float* b0  = (const float*)d_in[2];
    const float* g0  = (const float*)d_in[3];
    const float* be0 = (const float*)d_in[4];
    const float* W1  = (const float*)d_in[5];
    const float* b1  = (const float*)d_in[6];
    const float* g1  = (const float*)d_in[7];
    const float* be1 = (const float*)d_in[8];
    const float* Wp  = (const float*)d_in[9];
    const float* bp  = (const float*)d_in[10];
    float* out = (float*)d_out;

    cudaFuncSetAttribute(spline_fused_kernel,
                         cudaFuncAttributeMaxDynamicSharedMemorySize, SMEM_BYTES);
    spline_fused_kernel<<<kB / kRows, kThreads, SMEM_BYTES>>>(
        x, W0, b0, g0, be0, W1, b1, g1, be1, Wp, bp, out);
}

// round 8
// speedup vs baseline: 2.6448x; 1.1916x over previous
#include <cuda_runtime.h>

// ----------------------------------------------------------------------------
// SplineCoupling fused kernel, round 8: R7 with uniform barriers in phase 2.
// Per CTA: 128 rows, 512 threads, 1 CTA/SM (~197KB smem).
//  Phase 1: H1 = relu(LN(Xm @ W0 + b0)*g0+be0)      tile 4x8
//  Phase 2: H2 = relu(LN(H1 @ W1 + b1)*g1+be1)+H1   tile 8x8, 256 threads,
//           W1 staged via cp.async; H2 stored transposed (stride 132).
//  Phase 3: 4 super-chunks of 200 cols (8 dims). Wp streamed in 32-k slabs,
//           cp.async double-buffered. GEMM tile 8 rows x 8 cols (400 threads),
//           raw spilled per 64-row half, spline epilogue thread-per-(row,dim).
// ----------------------------------------------------------------------------

namespace {
constexpr int kB       = 262144;
constexpr int kThreads = 512;

// float offsets in dynamic smem
constexpr int XU_OFF  = 0;                    // 128*33 : xu -> yu
constexpr int BP_OFF  = XU_OFF + 4224;        // 800
constexpr int BV_OFF  = BP_OFF + 800;         // 768
constexpr int A_OFF   = BV_OFF + 768;         // 16896 : xm(33) -> H1(129) -> H2T(132)
constexpr int B_OFF   = A_OFF + 16896;        // 26624 : W0 / W1 / [Wq0|Wq1|raw]
constexpr int WQ0_OFF = B_OFF;                // 32*208 = 6656
constexpr int WQ1_OFF = B_OFF + 6656;
constexpr int RAW_OFF = B_OFF + 13312;        // 64*208 = 13312
constexpr int SMEM_FLOATS = B_OFF + 26624;    // 49312
constexpr int SMEM_BYTES  = SMEM_FLOATS * 4;  // 197248
}  // namespace

__device__ __forceinline__ void cp_async16(unsigned dst, const float4* src) {
    asm volatile("cp.async.cg.shared.global [%0], [%1], 16;" :: "r"(dst), "l"(src));
}
__device__ __forceinline__ void cp_commit() { asm volatile("cp.async.commit_group;"); }
__device__ __forceinline__ void cp_wait0()  { asm volatile("cp.async.wait_group 0;"); }

// RQS spline epilogue for one (row, dim). Reads 25 raw logits, updates xu->yu
// in-place, returns log-det contribution.
__device__ __forceinline__ float rqs_epilogue(const float* __restrict__ rawp,
                                              const float* __restrict__ bpd,
                                              float* __restrict__ xuslot)
{
    float wr[8], hr[8], dr9[9];
    #pragma unroll
    for (int j = 0; j < 8; j++) wr[j] = rawp[j] + bpd[j];
    #pragma unroll
    for (int j = 0; j < 8; j++) hr[j] = rawp[8 + j] + bpd[8 + j];
    #pragma unroll
    for (int j = 0; j < 9; j++) dr9[j] = rawp[16 + j] + bpd[16 + j];

    float mw = wr[0];
    #pragma unroll
    for (int j = 1; j < 8; j++) mw = fmaxf(mw, wr[j]);
    float ew[8], sw = 0.f;
    #pragma unroll
    for (int j = 0; j < 8; j++) { ew[j] = __expf(wr[j] - mw); sw += ew[j]; }
    float scw = 5.952f / sw;                 // (1 - 8*0.001) * 2*BOUND
    float w[8];
    #pragma unroll
    for (int j = 0; j < 8; j++) w[j] = 0.006f + ew[j] * scw;

    float mh = hr[0];
    #pragma unroll
    for (int j = 1; j < 8; j++) mh = fmaxf(mh, hr[j]);
    float eh[8], shs = 0.f;
    #pragma unroll
    for (int j = 0; j < 8; j++) { eh[j] = __expf(hr[j] - mh); shs += eh[j]; }
    float sch = 5.952f / shs;
    float h[8];
    #pragma unroll
    for (int j = 0; j < 8; j++) h[j] = 0.006f + eh[j] * sch;

    float dv[9];
    #pragma unroll
    for (int j = 0; j < 9; j++) {
        float xx = dr9[j];
        dv[j] = fmaxf(xx, 0.f) + __logf(1.f + __expf(-fabsf(xx))) + 0.001f;
    }

    float xu = *xuslot;
    bool inside = (xu > -3.f) && (xu < 3.f);
    float xc = fminf(fmaxf(xu, -3.f), 3.f);

    float cwv[9], chv[9];
    cwv[0] = -3.f; chv[0] = -3.f;
    #pragma unroll
    for (int j = 0; j < 8; j++) {
        cwv[j + 1] = cwv[j] + w[j];
        chv[j + 1] = chv[j] + h[j];
    }
    int idx = 0;
    #pragma unroll
    for (int j = 1; j <= 8; j++) idx += (xc >= cwv[j]) ? 1 : 0;
    idx = min(idx, 7);

    float w_k = w[0], x_k = cwv[0], h_k = h[0], y_k = chv[0];
    float d_k = dv[0], d_k1 = dv[1];
    #pragma unroll
    for (int j = 1; j < 8; j++) {
        if (idx == j) {
            w_k = w[j]; x_k = cwv[j]; h_k = h[j]; y_k = chv[j];
            d_k = dv[j]; d_k1 = dv[j + 1];
        }
    }
    float s   = h_k / w_k;
    float th  = (xc - x_k) / w_k;
    float om  = 1.f - th;
    float t1m = th * om;
    float den = s + (d_k1 + d_k - 2.f * s) * t1m;
    float yin = y_k + h_k * (s * th * th + d_k * t1m) / den;
    float num = d_k1 * th * th + 2.f * s * t1m + d_k * om * om;
    float ldin = 2.f * __logf(s) + __logf(num) - 2.f * __logf(den);

    *xuslot = inside ? yin : xu;
    return inside ? ldin : 0.f;
}

__global__ void __launch_bounds__(512, 1) spline_fused_kernel(
    const float* __restrict__ x,
    const float* __restrict__ W0, const float* __restrict__ b0,
    const float* __restrict__ g0, const float* __restrict__ be0,
    const float* __restrict__ W1, const float* __restrict__ b1,
    const float* __restrict__ g1, const float* __restrict__ be1,
    const float* __restrict__ Wp, const float* __restrict__ bp,
    float* __restrict__ out)
{
    extern __shared__ float sm[];
    float* sXU  = sm + XU_OFF;
    float* sBP  = sm + BP_OFF;
    float* sBV  = sm + BV_OFF;
    float* sA   = sm + A_OFF;    // xm -> H1 -> H2T
    float* sB   = sm + B_OFF;    // W0 -> W1 -> [Wq0|Wq1|raw]
    float* sRaw = sm + RAW_OFF;
    const unsigned smem_u32 = (unsigned)__cvta_generic_to_shared(sm);

    const int tid = threadIdx.x;
    const int r0  = blockIdx.x * 128;

    // ---------------- cooperative loads ----------------
    {
        const float4* xg = reinterpret_cast<const float4*>(x + (size_t)r0 * 64);
        #pragma unroll
        for (int i = tid; i < 128 * 16; i += kThreads) {
            int r = i >> 4, v = i & 15;
            float4 f = xg[i];
            sA [r * 33 + 2 * v]     = f.x;   // xm
            sXU[r * 33 + 2 * v]     = f.y;
            sA [r * 33 + 2 * v + 1] = f.z;
            sXU[r * 33 + 2 * v + 1] = f.w;
        }
        const float4* w0g = reinterpret_cast<const float4*>(W0);
        #pragma unroll
        for (int i = tid; i < 1024; i += kThreads)
            reinterpret_cast<float4*>(sB)[i] = w0g[i];
        const float4* bpg = reinterpret_cast<const float4*>(bp);
        #pragma unroll
        for (int i = tid; i < 200; i += kThreads)
            reinterpret_cast<float4*>(sBP)[i] = bpg[i];
        if (tid < 128) {
            sBV[tid]       = b0[tid];
            sBV[128 + tid] = g0[tid];
            sBV[256 + tid] = be0[tid];
            sBV[384 + tid] = b1[tid];
            sBV[512 + tid] = g1[tid];
            sBV[640 + tid] = be1[tid];
        }
    }
    __syncthreads();

    // ---------------- Phase 1: GEMM1 (K=32) tile 4x8 ----------------
    {
        const int rg = tid >> 4, cg = tid & 15;
        float acc[4][8];
        #pragma unroll
        for (int r = 0; r < 4; r++)
            #pragma unroll
            for (int i = 0; i < 8; i++) acc[r][i] = 0.f;

        #pragma unroll 4
        for (int k = 0; k < 32; k++) {
            float a[4];
            #pragma unroll
            for (int r = 0; r < 4; r++) a[r] = sA[(rg * 4 + r) * 33 + k];
            #pragma unroll
            for (int i = 0; i < 8; i++) {
                float b = sB[k * 128 + cg + 16 * i];
                #pragma unroll
                for (int r = 0; r < 4; r++) acc[r][i] += a[r] * b;
            }
        }
        __syncthreads();   // xm & W0 reads done

        // kick W1 into sB via cp.async (overlaps LN + H1 store)
        {
            const float4* w1g = reinterpret_cast<const float4*>(W1);
            #pragma unroll
            for (int i = tid; i < 4096; i += kThreads)
                cp_async16(smem_u32 + (unsigned)(B_OFF + i * 4) * 4u, w1g + i);
            cp_commit();
        }

        float mu[4], rs[4];
        #pragma unroll
        for (int r = 0; r < 4; r++) {
            float s1 = 0.f, s2 = 0.f;
            #pragma unroll
            for (int i = 0; i < 8; i++) {
                float v = acc[r][i] + sBV[cg + 16 * i];
                acc[r][i] = v;
                s1 += v; s2 += v * v;
            }
            #pragma unroll
            for (int d = 1; d < 16; d <<= 1) {
                s1 += __shfl_xor_sync(0xffffffffu, s1, d);
                s2 += __shfl_xor_sync(0xffffffffu, s2, d);
            }
            mu[r] = s1 * (1.f / 128.f);
            rs[r] = rsqrtf(s2 * (1.f / 128.f) - mu[r] * mu[r] + 1e-6f);
        }
        #pragma unroll
        for (int i = 0; i < 8; i++) {
            int c = cg + 16 * i;
            float gg = sBV[128 + c], bb = sBV[256 + c];
            #pragma unroll
            for (int r = 0; r < 4; r++) {
                float h = (acc[r][i] - mu[r]) * rs[r] * gg + bb;
                sA[(rg * 4 + r) * 129 + c] = fmaxf(h, 0.f);   // H1
            }
        }
    }
    cp_wait0();
    __syncthreads();

    // ---------------- Phase 2: GEMM2 (K=128) tile 8x8, 256 threads ---------
    // Uniform-barrier structure: compute (divergent, no barriers) ->
    // uniform sync -> store (divergent, no barriers) -> uniform sync.
    {
        const bool p2  = tid < 256;
        const int rg2  = tid >> 4;           // 0..15 for p2
        const int cg2  = tid & 15;
        float a2[8][8];
        if (p2) {
            #pragma unroll
            for (int r = 0; r < 8; r++)
                #pragma unroll
                for (int j = 0; j < 8; j++) a2[r][j] = 0.f;

            #pragma unroll 2
            for (int k = 0; k < 128; k++) {
                float bv_[8];
                #pragma unroll
                for (int j = 0; j < 8; j++) bv_[j] = sB[k * 128 + 16 * j + cg2];
                #pragma unroll
                for (int r = 0; r < 8; r++) {
                    float av = sA[(rg2 * 8 + r) * 129 + k];
                    #pragma unroll
                    for (int j = 0; j < 8; j++) a2[r][j] += av * bv_[j];
                }
            }
            // bias + LN + relu + residual (into a2); shuffles stay in-warp
            #pragma unroll
            for (int r = 0; r < 8; r++) {
                float s1 = 0.f, s2 = 0.f;
                #pragma unroll
                for (int j = 0; j < 8; j++) {
                    float v = a2[r][j] + sBV[384 + 16 * j + cg2];
                    a2[r][j] = v;
                    s1 += v; s2 += v * v;
                }
                #pragma unroll
                for (int d = 1; d < 16; d <<= 1) {
                    s1 += __shfl_xor_sync(0xffffffffu, s1, d);
                    s2 += __shfl_xor_sync(0xffffffffu, s2, d);
                }
                float mu = s1 * (1.f / 128.f);
                float rs = rsqrtf(s2 * (1.f / 128.f) - mu * mu + 1e-6f);
                #pragma unroll
                for (int j = 0; j < 8; j++) {
                    int c = 16 * j + cg2;
                    float h = fmaxf((a2[r][j] - mu) * rs * sBV[512 + c] + sBV[640 + c], 0.f)
                              + sA[(rg2 * 8 + r) * 129 + c];    // residual (H1 read)
                    a2[r][j] = h;
                }
            }
        }
        __syncthreads();   // all H1 reads complete (uniform barrier)
        if (p2) {
            #pragma unroll
            for (int r = 0; r < 8; r++)
                #pragma unroll
                for (int j = 0; j < 8; j++)
                    sA[(16 * j + cg2) * 132 + rg2 * 8 + r] = a2[r][j];   // H2T
        }
    }
    __syncthreads();

    // ---------------- Phase 3: 4 super-chunks x 4 k-slabs ----------------
    const int rg3 = tid / 25;
    const int cg3 = tid - rg3 * 25;
    const bool act = tid < 400;
    float ldA = 0.f, ldB = 0.f;
    float acc[8][8];

    // slab g (g = sc*4 + s) -> buffer g&1
    auto issue_slab = [&](int g) {
        int sc = g >> 2, s = g & 3;
        const float* src0 = Wp + (size_t)(s * 32) * 800 + sc * 200;
        unsigned dstb = smem_u32 + (unsigned)((g & 1) ? WQ1_OFF : WQ0_OFF) * 4u;
        #pragma unroll
        for (int i = tid; i < 1600; i += kThreads) {
            int kk = i / 50, cc = i - kk * 50;
            cp_async16(dstb + (unsigned)(kk * 208 + cc * 4) * 4u,
                       reinterpret_cast<const float4*>(src0 + kk * 800 + cc * 4));
        }
        cp_commit();
    };
    issue_slab(0);

    for (int g = 0; g < 16; g++) {
        cp_wait0();
        __syncthreads();
        if (g < 15) issue_slab(g + 1);
        if ((g & 3) == 0) {
            #pragma unroll
            for (int r = 0; r < 8; r++)
                #pragma unroll
                for (int j = 0; j < 8; j++) acc[r][j] = 0.f;
        }
        const float* wq = sm + ((g & 1) ? WQ1_OFF : WQ0_OFF);
        if (act) {
            const float* ab = sA + (g & 3) * 32 * 132 + rg3 * 8;
            const float* bb = wq + cg3 * 4;
            #pragma unroll 2
            for (int kk = 0; kk < 32; kk++) {
                float4 b0 = *reinterpret_cast<const float4*>(bb + kk * 208);
                float4 b1 = *reinterpret_cast<const float4*>(bb + kk * 208 + 100);
                float4 a0 = *reinterpret_cast<const float4*>(ab + kk * 132);
                float4 a1 = *reinterpret_cast<const float4*>(ab + kk * 132 + 4);
                float av[8] = {a0.x, a0.y, a0.z, a0.w, a1.x, a1.y, a1.z, a1.w};
                #pragma unroll
                for (int r = 0; r < 8; r++) {
                    acc[r][0] += av[r] * b0.x;
                    acc[r][1] += av[r] * b0.y;
                    acc[r][2] += av[r] * b0.z;
                    acc[r][3] += av[r] * b0.w;
                    acc[r][4] += av[r] * b1.x;
                    acc[r][5] += av[r] * b1.y;
                    acc[r][6] += av[r] * b1.z;
                    acc[r][7] += av[r] * b1.w;
                }
            }
        }
        if ((g & 3) == 3) {
            const int sc = g >> 2;
            // half A (rows 0..63): written by tids 0..199 (rg3 < 8)
            if (act && rg3 < 8) {
                #pragma unroll
                for (int r = 0; r < 8; r++) {
                    int lr = rg3 * 8 + r;
                    *reinterpret_cast<float4*>(sRaw + lr * 208 + cg3 * 4) =
                        make_float4(acc[r][0], acc[r][1], acc[r][2], acc[r][3]);
                    *reinterpret_cast<float4*>(sRaw + lr * 208 + 100 + cg3 * 4) =
                        make_float4(acc[r][4], acc[r][5], acc[r][6], acc[r][7]);
                }
            }
            __syncthreads();
            {
                int lr = tid >> 3, ed = tid & 7;
                ldA += rqs_epilogue(sRaw + lr * 208 + ed * 25,
                                    sBP + (sc * 8 + ed) * 25,
                                    sXU + lr * 33 + sc * 8 + ed);
            }
            __syncthreads();
            // half B (rows 64..127): written by tids 200..399 (rg3 >= 8)
            if (act && rg3 >= 8) {
                #pragma unroll
                for (int r = 0; r < 8; r++) {
                    int lr = (rg3 - 8) * 8 + r;
                    *reinterpret_cast<float4*>(sRaw + lr * 208 + cg3 * 4) =
                        make_float4(acc[r][0], acc[r][1], acc[r][2], acc[r][3]);
                    *reinterpret_cast<float4*>(sRaw + lr * 208 + 100 + cg3 * 4) =
                        make_float4(acc[r][4], acc[r][5], acc[r][6], acc[r][7]);
                }
            }
            __syncthreads();
            {
                int lr = tid >> 3, ed = tid & 7;
                ldB += rqs_epilogue(sRaw + lr * 208 + ed * 25,
                                    sBP + (sc * 8 + ed) * 25,
                                    sXU + (64 + lr) * 33 + sc * 8 + ed);
            }
            __syncthreads();
        }
    }

    // log_det: reduce over 8 dim-threads of each row (in-warp groups of 8)
    #pragma unroll
    for (int d = 1; d < 8; d <<= 1) {
        ldA += __shfl_xor_sync(0xffffffffu, ldA, d);
        ldB += __shfl_xor_sync(0xffffffffu, ldB, d);
    }
    if ((tid & 7) == 0) {
        out[(size_t)kB * 64 + r0 + (tid >> 3)]      = ldA;
        out[(size_t)kB * 64 + r0 + 64 + (tid >> 3)] = ldB;
    }

    // final y: re-read x for xm, interleave with yu; float4 coalesced
    {
        const float4* xg = reinterpret_cast<const float4*>(x + (size_t)r0 * 64);
        float4* og = reinterpret_cast<float4*>(out + (size_t)r0 * 64);
        #pragma unroll
        for (int i = tid; i < 128 * 16; i += kThreads) {
            int r = i >> 4, v = i & 15;
            float4 f = xg[i];
            og[i] = make_float4(f.x, sXU[r * 33 + 2 * v],
                                f.z, sXU[r * 33 + 2 * v + 1]);
        }
    }
}

extern "C" void kernel_launch(void* const* d_in, const int* in_sizes, int n_in,
                              void* d_out, int out_size)
{
    (void)in_sizes; (void)n_in; (void)out_size;
    const float* x   = (const float*)d_in[0];
    const float* W0  = (const float*)d_in[1];
    const float* b0  = (const float*)d_in[2];
    const float* g0  = (const float*)d_in[3];
    const float* be0 = (const float*)d_in[4];
    const float* W1  = (const float*)d_in[5];
    const float* b1  = (const float*)d_in[6];
    const float* g1  = (const float*)d_in[7];
    const float* be1 = (const float*)d_in[8];
    const float* Wp  = (const float*)d_in[9];
    const float* bp  = (const float*)d_in[10];
    float* out = (float*)d_out;

    cudaFuncSetAttribute(spline_fused_kernel,
                         cudaFuncAttributeMaxDynamicSharedMemorySize, SMEM_BYTES);
    spline_fused_kernel<<<kB / 128, kThreads, SMEM_BYTES>>>(
        x, W0, b0, g0, be0, W1, b1, g1, be1, Wp, bp, out);
}

// round 11
// speedup vs baseline: 4.3573x; 1.6475x over previous
#include <cuda_runtime.h>
#include <cuda_bf16.h>

// ----------------------------------------------------------------------------
// SplineCoupling fused kernel, round 11: R10 retry (infra failure suspected).
// GEMM3 on legacy tensor cores (mma.sync.m16n8k16 bf16, 2-term split, 3
// passes), phases 1-2 FFMA. Per CTA: 128 rows, 512 threads, ~203KB smem.
// Only change vs R10: next-chunk B staging issued before the epilogue.
// ----------------------------------------------------------------------------

namespace {
constexpr int kB       = 262144;
constexpr int kThreads = 512;

// byte offsets in dynamic smem
constexpr int XU_B  = 0;        // 16896 : xu -> yu (128*33 f32)
constexpr int BP_B  = 16896;    // 3200  : bp
constexpr int BV_B  = 20096;    // 3072  : b0,g0,be0,b1,g1,be1
constexpr int AHI_B = 23296;    // 34816 : A_hi bf16 [m][k] stride 136 (272B)
constexpr int ALO_B = 58112;    // 34816 : A_lo
constexpr int BHI_B = 92928;    // 30720 : B_hi bf16 [k][n] stride 120 (240B)
constexpr int BLO_B = 123648;   // 30720 : B_lo
constexpr int RAW_B = 154368;   // 53760 : raw logits f32 [row][105]
constexpr int SMEM_BYTES = 208128;
// phase 1-2 overlays
constexpr int W_B = AHI_B;      // W0 (16KB) then W1 (64KB) fp32
constexpr int H_B = BHI_B;      // xm (row*33) then H1 (row*129) fp32
}  // namespace

__device__ __forceinline__ void cp_async16(unsigned dst, const float4* src) {
    asm volatile("cp.async.cg.shared.global [%0], [%1], 16;" :: "r"(dst), "l"(src));
}
__device__ __forceinline__ void cp_commit() { asm volatile("cp.async.commit_group;"); }
__device__ __forceinline__ void cp_wait0()  { asm volatile("cp.async.wait_group 0;"); }

__device__ __forceinline__ void ldsm_x4(unsigned addr, unsigned& r0, unsigned& r1,
                                        unsigned& r2, unsigned& r3) {
    asm volatile("ldmatrix.sync.aligned.m8n8.x4.shared.b16 {%0,%1,%2,%3}, [%4];"
                 : "=r"(r0), "=r"(r1), "=r"(r2), "=r"(r3) : "r"(addr));
}
__device__ __forceinline__ void ldsm_x2t(unsigned addr, unsigned& r0, unsigned& r1) {
    asm volatile("ldmatrix.sync.aligned.m8n8.x2.trans.shared.b16 {%0,%1}, [%2];"
                 : "=r"(r0), "=r"(r1) : "r"(addr));
}
__device__ __forceinline__ void mma16816(float* d, const unsigned* a,
                                         unsigned b0, unsigned b1) {
    asm volatile(
        "mma.sync.aligned.m16n8k16.row.col.f32.bf16.bf16.f32 "
        "{%0,%1,%2,%3}, {%4,%5,%6,%7}, {%8,%9}, {%0,%1,%2,%3};"
        : "+f"(d[0]), "+f"(d[1]), "+f"(d[2]), "+f"(d[3])
        : "r"(a[0]), "r"(a[1]), "r"(a[2]), "r"(a[3]), "r"(b0), "r"(b1));
}
__device__ __forceinline__ unsigned pack_bf2(__nv_bfloat16 a, __nv_bfloat16 b) {
    return ((unsigned)__bfloat16_as_ushort(b) << 16) | __bfloat16_as_ushort(a);
}

// RQS spline epilogue for one (row, dim): proven numerics from R6/R8.
__device__ __forceinline__ float rqs_epilogue(const float* __restrict__ rawp,
                                              const float* __restrict__ bpd,
                                              float* __restrict__ xuslot)
{
    float wr[8], hr[8], dr9[9];
    #pragma unroll
    for (int j = 0; j < 8; j++) wr[j] = rawp[j] + bpd[j];
    #pragma unroll
    for (int j = 0; j < 8; j++) hr[j] = rawp[8 + j] + bpd[8 + j];
    #pragma unroll
    for (int j = 0; j < 9; j++) dr9[j] = rawp[16 + j] + bpd[16 + j];

    float mw = wr[0];
    #pragma unroll
    for (int j = 1; j < 8; j++) mw = fmaxf(mw, wr[j]);
    float ew[8], sw = 0.f;
    #pragma unroll
    for (int j = 0; j < 8; j++) { ew[j] = __expf(wr[j] - mw); sw += ew[j]; }
    float scw = 5.952f / sw;
    float w[8];
    #pragma unroll
    for (int j = 0; j < 8; j++) w[j] = 0.006f + ew[j] * scw;

    float mh = hr[0];
    #pragma unroll
    for (int j = 1; j < 8; j++) mh = fmaxf(mh, hr[j]);
    float eh[8], shs = 0.f;
    #pragma unroll
    for (int j = 0; j < 8; j++) { eh[j] = __expf(hr[j] - mh); shs += eh[j]; }
    float sch = 5.952f / shs;
    float h[8];
    #pragma unroll
    for (int j = 0; j < 8; j++) h[j] = 0.006f + eh[j] * sch;

    float dv[9];
    #pragma unroll
    for (int j = 0; j < 9; j++) {
        float xx = dr9[j];
        dv[j] = fmaxf(xx, 0.f) + __logf(1.f + __expf(-fabsf(xx))) + 0.001f;
    }

    float xu = *xuslot;
    bool inside = (xu > -3.f) && (xu < 3.f);
    float xc = fminf(fmaxf(xu, -3.f), 3.f);

    float cwv[9], chv[9];
    cwv[0] = -3.f; chv[0] = -3.f;
    #pragma unroll
    for (int j = 0; j < 8; j++) {
        cwv[j + 1] = cwv[j] + w[j];
        chv[j + 1] = chv[j] + h[j];
    }
    int idx = 0;
    #pragma unroll
    for (int j = 1; j <= 8; j++) idx += (xc >= cwv[j]) ? 1 : 0;
    idx = min(idx, 7);

    float w_k = w[0], x_k = cwv[0], h_k = h[0], y_k = chv[0];
    float d_k = dv[0], d_k1 = dv[1];
    #pragma unroll
    for (int j = 1; j < 8; j++) {
        if (idx == j) {
            w_k = w[j]; x_k = cwv[j]; h_k = h[j]; y_k = chv[j];
            d_k = dv[j]; d_k1 = dv[j + 1];
        }
    }
    float s   = h_k / w_k;
    float th  = (xc - x_k) / w_k;
    float om  = 1.f - th;
    float t1m = th * om;
    float den = s + (d_k1 + d_k - 2.f * s) * t1m;
    float yin = y_k + h_k * (s * th * th + d_k * t1m) / den;
    float num = d_k1 * th * th + 2.f * s * t1m + d_k * om * om;
    float ldin = 2.f * __logf(s) + __logf(num) - 2.f * __logf(den);

    *xuslot = inside ? yin : xu;
    return inside ? ldin : 0.f;
}

__global__ void __launch_bounds__(512, 1) spline_fused_kernel(
    const float* __restrict__ x,
    const float* __restrict__ W0, const float* __restrict__ b0,
    const float* __restrict__ g0, const float* __restrict__ be0,
    const float* __restrict__ W1, const float* __restrict__ b1,
    const float* __restrict__ g1, const float* __restrict__ be1,
    const float* __restrict__ Wp, const float* __restrict__ bp,
    float* __restrict__ out)
{
    extern __shared__ char smc[];
    float* sXU  = reinterpret_cast<float*>(smc + XU_B);
    float* sBP  = reinterpret_cast<float*>(smc + BP_B);
    float* sBV  = reinterpret_cast<float*>(smc + BV_B);
    float* sW   = reinterpret_cast<float*>(smc + W_B);   // W0 -> W1 (fp32)
    float* sH   = reinterpret_cast<float*>(smc + H_B);   // xm -> H1 (fp32)
    float* sRaw = reinterpret_cast<float*>(smc + RAW_B);
    const unsigned smem_u32 = (unsigned)__cvta_generic_to_shared(smc);

    const int tid  = threadIdx.x;
    const int wid  = tid >> 5;
    const int lane = tid & 31;
    const int r0   = blockIdx.x * 128;

    // ---------------- cooperative loads ----------------
    {
        const float4* xg = reinterpret_cast<const float4*>(x + (size_t)r0 * 64);
        #pragma unroll
        for (int i = tid; i < 128 * 16; i += kThreads) {
            int r = i >> 4, v = i & 15;
            float4 f = xg[i];
            sH [r * 33 + 2 * v]     = f.x;   // xm
            sXU[r * 33 + 2 * v]     = f.y;
            sH [r * 33 + 2 * v + 1] = f.z;
            sXU[r * 33 + 2 * v + 1] = f.w;
        }
        const float4* w0g = reinterpret_cast<const float4*>(W0);
        #pragma unroll
        for (int i = tid; i < 1024; i += kThreads)
            reinterpret_cast<float4*>(sW)[i] = w0g[i];
        const float4* bpg = reinterpret_cast<const float4*>(bp);
        #pragma unroll
        for (int i = tid; i < 200; i += kThreads)
            reinterpret_cast<float4*>(sBP)[i] = bpg[i];
        if (tid < 128) {
            sBV[tid]       = b0[tid];
            sBV[128 + tid] = g0[tid];
            sBV[256 + tid] = be0[tid];
            sBV[384 + tid] = b1[tid];
            sBV[512 + tid] = g1[tid];
            sBV[640 + tid] = be1[tid];
        }
    }
    __syncthreads();

    // ---------------- Phase 1: GEMM1 (K=32) tile 4x8 ----------------
    {
        const int rg = tid >> 4, cg = tid & 15;
        float acc1[4][8];
        #pragma unroll
        for (int r = 0; r < 4; r++)
            #pragma unroll
            for (int i = 0; i < 8; i++) acc1[r][i] = 0.f;

        #pragma unroll 4
        for (int k = 0; k < 32; k++) {
            float a[4];
            #pragma unroll
            for (int r = 0; r < 4; r++) a[r] = sH[(rg * 4 + r) * 33 + k];
            #pragma unroll
            for (int i = 0; i < 8; i++) {
                float b = sW[k * 128 + cg + 16 * i];
                #pragma unroll
                for (int r = 0; r < 4; r++) acc1[r][i] += a[r] * b;
            }
        }
        __syncthreads();   // xm & W0 reads done

        {   // kick W1 into sW via cp.async
            const float4* w1g = reinterpret_cast<const float4*>(W1);
            #pragma unroll
            for (int i = tid; i < 4096; i += kThreads)
                cp_async16(smem_u32 + (unsigned)(W_B + i * 16), w1g + i);
            cp_commit();
        }

        float mu[4], rs[4];
        #pragma unroll
        for (int r = 0; r < 4; r++) {
            float s1 = 0.f, s2 = 0.f;
            #pragma unroll
            for (int i = 0; i < 8; i++) {
                float v = acc1[r][i] + sBV[cg + 16 * i];
                acc1[r][i] = v;
                s1 += v; s2 += v * v;
            }
            #pragma unroll
            for (int d = 1; d < 16; d <<= 1) {
                s1 += __shfl_xor_sync(0xffffffffu, s1, d);
                s2 += __shfl_xor_sync(0xffffffffu, s2, d);
            }
            mu[r] = s1 * (1.f / 128.f);
            rs[r] = rsqrtf(s2 * (1.f / 128.f) - mu[r] * mu[r] + 1e-6f);
        }
        #pragma unroll
        for (int i = 0; i < 8; i++) {
            int c = cg + 16 * i;
            float gg = sBV[128 + c], bb = sBV[256 + c];
            #pragma unroll
            for (int r = 0; r < 4; r++) {
                float h = (acc1[r][i] - mu[r]) * rs[r] * gg + bb;
                sH[(rg * 4 + r) * 129 + c] = fmaxf(h, 0.f);   // H1
            }
        }
    }
    cp_wait0();
    __syncthreads();

    // ---------------- Phase 2: GEMM2 (K=128) tile 8x8, 256 threads ---------
    {
        const bool p2  = tid < 256;
        const int rg2  = tid >> 4;
        const int cg2  = tid & 15;
        float a2[8][8];
        if (p2) {
            #pragma unroll
            for (int r = 0; r < 8; r++)
                #pragma unroll
                for (int j = 0; j < 8; j++) a2[r][j] = 0.f;

            #pragma unroll 2
            for (int k = 0; k < 128; k++) {
                float bv_[8];
                #pragma unroll
                for (int j = 0; j < 8; j++) bv_[j] = sW[k * 128 + 16 * j + cg2];
                #pragma unroll
                for (int r = 0; r < 8; r++) {
                    float av = sH[(rg2 * 8 + r) * 129 + k];
                    #pragma unroll
                    for (int j = 0; j < 8; j++) a2[r][j] += av * bv_[j];
                }
            }
            #pragma unroll
            for (int r = 0; r < 8; r++) {
                float s1 = 0.f, s2 = 0.f;
                #pragma unroll
                for (int j = 0; j < 8; j++) {
                    float v = a2[r][j] + sBV[384 + 16 * j + cg2];
                    a2[r][j] = v;
                    s1 += v; s2 += v * v;
                }
                #pragma unroll
                for (int d = 1; d < 16; d <<= 1) {
                    s1 += __shfl_xor_sync(0xffffffffu, s1, d);
                    s2 += __shfl_xor_sync(0xffffffffu, s2, d);
                }
                float mu = s1 * (1.f / 128.f);
                float rs = rsqrtf(s2 * (1.f / 128.f) - mu * mu + 1e-6f);
                #pragma unroll
                for (int j = 0; j < 8; j++) {
                    int c = 16 * j + cg2;
                    float h = fmaxf((a2[r][j] - mu) * rs * sBV[512 + c] + sBV[640 + c], 0.f)
                              + sH[(rg2 * 8 + r) * 129 + c];    // residual
                    a2[r][j] = h;
                }
            }
        }
        __syncthreads();   // all W1 + H1 reads complete (uniform barrier)
        if (p2) {
            // H2 -> A_hi/A_lo bf16, [m][k] row-major stride 136
            #pragma unroll
            for (int r = 0; r < 8; r++) {
                int m = rg2 * 8 + r;
                #pragma unroll
                for (int j = 0; j < 8; j++) {
                    int k = 16 * j + cg2;
                    float v = a2[r][j];
                    __nv_bfloat16 hi = __float2bfloat16(v);
                    __nv_bfloat16 lo = __float2bfloat16(v - __bfloat162float(hi));
                    *reinterpret_cast<unsigned short*>(smc + AHI_B + m * 272 + k * 2) =
                        __bfloat16_as_ushort(hi);
                    *reinterpret_cast<unsigned short*>(smc + ALO_B + m * 272 + k * 2) =
                        __bfloat16_as_ushort(lo);
                }
            }
        }
        // zero B pad cols 100..103 for all 128 k rows (512 threads = 128*4)
        {
            int k = tid >> 2, n = 100 + (tid & 3);
            *reinterpret_cast<unsigned short*>(smc + BHI_B + k * 240 + n * 2) = 0;
            *reinterpret_cast<unsigned short*>(smc + BLO_B + k * 240 + n * 2) = 0;
        }
    }

    // ---------------- Phase 3: 8 chunks of 100 cols, mma.sync --------------
    auto stage_b = [&](int c) {
        const float* src = Wp + c * 100;
        for (int i = tid; i < 3200; i += kThreads) {
            int k = i / 25, n4 = i - k * 25;
            float4 v = *reinterpret_cast<const float4*>(src + k * 800 + n4 * 4);
            __nv_bfloat16 h0 = __float2bfloat16(v.x);
            __nv_bfloat16 h1 = __float2bfloat16(v.y);
            __nv_bfloat16 h2 = __float2bfloat16(v.z);
            __nv_bfloat16 h3 = __float2bfloat16(v.w);
            __nv_bfloat16 l0 = __float2bfloat16(v.x - __bfloat162float(h0));
            __nv_bfloat16 l1 = __float2bfloat16(v.y - __bfloat162float(h1));
            __nv_bfloat16 l2 = __float2bfloat16(v.z - __bfloat162float(h2));
            __nv_bfloat16 l3 = __float2bfloat16(v.w - __bfloat162float(h3));
            *reinterpret_cast<uint2*>(smc + BHI_B + k * 240 + n4 * 8) =
                make_uint2(pack_bf2(h0, h1), pack_bf2(h2, h3));
            *reinterpret_cast<uint2*>(smc + BLO_B + k * 240 + n4 * 8) =
                make_uint2(pack_bf2(l0, l1), pack_bf2(l2, l3));
        }
    };
    stage_b(0);
    __syncthreads();

    // ldmatrix lane offsets (bytes)
    const unsigned aoff = (unsigned)(((((lane >> 3) & 1) * 8) + (lane & 7)) * 272
                                     + ((lane >> 4) * 8) * 2);
    const unsigned boff = (unsigned)(((((lane >> 3) & 1) * 8) + (lane & 7)) * 240);
    const int mg = wid & 3, hh = wid >> 2;    // GEMM warps: wid < 8
    const int erow = tid >> 2, eq = tid & 3;
    float ld_acc = 0.f;

    for (int c = 0; c < 8; c++) {
        if (wid < 8) {
            float acc[2][7][4];
            #pragma unroll
            for (int mt = 0; mt < 2; mt++)
                #pragma unroll
                for (int nt = 0; nt < 7; nt++)
                    #pragma unroll
                    for (int q = 0; q < 4; q++) acc[mt][nt][q] = 0.f;

            const unsigned aHi0 = smem_u32 + AHI_B + (unsigned)(mg * 32) * 272u + aoff;
            const unsigned aLo0 = smem_u32 + ALO_B + (unsigned)(mg * 32) * 272u + aoff;
            const unsigned bHi0 = smem_u32 + BHI_B + (unsigned)(hh * 112) + boff;
            const unsigned bLo0 = smem_u32 + BLO_B + (unsigned)(hh * 112) + boff;

            // pass A: (Ahi + Alo) x Bhi  (Bhi loaded once per tile)
            #pragma unroll
            for (int ks = 0; ks < 8; ks++) {
                unsigned ah[2][4], al[2][4];
                #pragma unroll
                for (int mt = 0; mt < 2; mt++) {
                    ldsm_x4(aHi0 + (unsigned)(mt * 16 * 272 + ks * 32),
                            ah[mt][0], ah[mt][1], ah[mt][2], ah[mt][3]);
                    ldsm_x4(aLo0 + (unsigned)(mt * 16 * 272 + ks * 32),
                            al[mt][0], al[mt][1], al[mt][2], al[mt][3]);
                }
                #pragma unroll
                for (int nt = 0; nt < 7; nt++) {
                    if (hh == 1 && nt == 6) continue;      // ntile 13: all pad
                    unsigned b0, b1;
                    ldsm_x2t(bHi0 + (unsigned)(ks * 3840 + nt * 16), b0, b1);
                    #pragma unroll
                    for (int mt = 0; mt < 2; mt++) {
                        mma16816(acc[mt][nt], ah[mt], b0, b1);
                        mma16816(acc[mt][nt], al[mt], b0, b1);
                    }
                }
            }
            // pass B: Ahi x Blo
            #pragma unroll
            for (int ks = 0; ks < 8; ks++) {
                unsigned ah[2][4];
                #pragma unroll
                for (int mt = 0; mt < 2; mt++)
                    ldsm_x4(aHi0 + (unsigned)(mt * 16 * 272 + ks * 32),
                            ah[mt][0], ah[mt][1], ah[mt][2], ah[mt][3]);
                #pragma unroll
                for (int nt = 0; nt < 7; nt++) {
                    if (hh == 1 && nt == 6) continue;
                    unsigned b0, b1;
                    ldsm_x2t(bLo0 + (unsigned)(ks * 3840 + nt * 16), b0, b1);
                    #pragma unroll
                    for (int mt = 0; mt < 2; mt++)
                        mma16816(acc[mt][nt], ah[mt], b0, b1);
                }
            }
            // D fragments -> raw (stride 105)
            #pragma unroll
            for (int mt = 0; mt < 2; mt++)
                #pragma unroll
                for (int nt = 0; nt < 7; nt++) {
                    int col = hh * 56 + nt * 8 + 2 * (lane & 3);
                    if (col < 100) {
                        int row = mg * 32 + mt * 16 + (lane >> 2);
                        sRaw[row * 105 + col]           = acc[mt][nt][0];
                        sRaw[row * 105 + col + 1]       = acc[mt][nt][1];
                        sRaw[(row + 8) * 105 + col]     = acc[mt][nt][2];
                        sRaw[(row + 8) * 105 + col + 1] = acc[mt][nt][3];
                    }
                }
        }
        __syncthreads();

        // stage next chunk first (gmem latency hides under epilogue compute);
        // B smem reads for chunk c finished before the barrier above.
        if (c < 7) stage_b(c + 1);

        // spline epilogue (all 512 threads = 128 rows x 4 dims)
        ld_acc += rqs_epilogue(sRaw + erow * 105 + eq * 25,
                               sBP + (c * 4 + eq) * 25,
                               sXU + erow * 33 + c * 4 + eq);
        __syncthreads();
    }

    // log_det: reduce over the 4 dim-threads of each row
    ld_acc += __shfl_xor_sync(0xffffffffu, ld_acc, 1);
    ld_acc += __shfl_xor_sync(0xffffffffu, ld_acc, 2);
    if (eq == 0) out[(size_t)kB * 64 + r0 + erow] = ld_acc;

    // final y: re-read x for xm, interleave with yu; float4 coalesced
    {
        const float4* xg = reinterpret_cast<const float4*>(x + (size_t)r0 * 64);
        float4* og = reinterpret_cast<float4*>(out + (size_t)r0 * 64);
        #pragma unroll
        for (int i = tid; i < 128 * 16; i += kThreads) {
            int r = i >> 4, v = i & 15;
            float4 f = xg[i];
            og[i] = make_float4(f.x, sXU[r * 33 + 2 * v],
                                f.z, sXU[r * 33 + 2 * v + 1]);
        }
    }
}

extern "C" void kernel_launch(void* const* d_in, const int* in_sizes, int n_in,
                              void* d_out, int out_size)
{
    (void)in_sizes; (void)n_in; (void)out_size;
    const float* x   = (const float*)d_in[0];
    const float* W0  = (const float*)d_in[1];
    const float* b0  = (const float*)d_in[2];
    const float* g0  = (const float*)d_in[3];
    const float* be0 = (const float*)d_in[4];
    const float* W1  = (const float*)d_in[5];
    const float* b1  = (const float*)d_in[6];
    const float* g1  = (const float*)d_in[7];
    const float* be1 = (const float*)d_in[8];
    const float* Wp  = (const float*)d_in[9];
    const float* bp  = (const float*)d_in[10];
    float* out = (float*)d_out;

    cudaFuncSetAttribute(spline_fused_kernel,
                         cudaFuncAttributeMaxDynamicSharedMemorySize, SMEM_BYTES);
    spline_fused_kernel<<<kB / 128, kThreads, SMEM_BYTES>>>(
        x, W0, b0, g0, be0, W1, b1, g1, be1, Wp, bp, out);
}